// round 9
// baseline (speedup 1.0000x reference)
#include <cuda_runtime.h>
#include <cuda_fp16.h>
#include <math.h>
#include <stdint.h>

#define BATCH 256
#define SEQ   720
#define CH    321
#define CUTF  200
#define FOUT  400

#define KD 768    // padded K stage1 (time 720)
#define KX 448    // padded K stage2 (2*CUTF=400)
#define KO 832    // padded K stage3 (2*FOUT=800)
#define N1 512    // padded N stage1
#define N3 768    // padded N stage3

#define RSB 80            // smem row stride bytes (32 fp16 + 16 pad)
#define TB  (128 * RSB)   // one tile: 10240 B
#define SMEM_BYTES (9 * TB)  // 3 stages x 3 tiles = 92160

typedef unsigned int u32;
typedef uint16_t u16;

// ---------------- device scratch ---------------------------------------------
__device__ __align__(256) __half d_Eh[(size_t)N1 * KD];   // twiddle hi
__device__ __align__(256) __half d_El[(size_t)N1 * KD];   // twiddle lo
__device__ __align__(256) __half d_Fh[(size_t)N3 * KO];
__device__ __align__(256) __half d_Fl[(size_t)N3 * KO];
__device__ __align__(256) __half d_xn[(size_t)CH * BATCH * KD];   // normalized input
__device__ __align__(256) __half d_X[(size_t)CH * BATCH * KX];    // DFT out (interleaved re/im)
__device__ __align__(256) __half d_O[(size_t)CH * BATCH * KO];    // mixer out
__device__ __align__(256) float d_y[(size_t)CH * BATCH * SEQ];
__device__ float d_mean[BATCH * CH];
__device__ float d_stdev[BATCH * CH];
__device__ float d_invstd[BATCH * CH];

// ---------------- helpers ----------------------------------------------------
__device__ __forceinline__ u32 s2u(const void* p) {
    u32 a;
    asm("{ .reg .u64 t; cvta.to.shared.u64 t, %1; cvt.u32.u64 %0, t; }" : "=r"(a) : "l"(p));
    return a;
}
__device__ __forceinline__ void cpa16(u32 dst, const void* src) {
    asm volatile("cp.async.ca.shared.global [%0], [%1], 16;" :: "r"(dst), "l"(src));
}
__device__ __forceinline__ void cp_commit() { asm volatile("cp.async.commit_group;"); }
__device__ __forceinline__ void cp_wait1() { asm volatile("cp.async.wait_group 1;"); }
__device__ __forceinline__ void cp_wait0() { asm volatile("cp.async.wait_group 0;"); }
__device__ __forceinline__ void ldsm4(u32 a[4], u32 addr) {
    asm volatile("ldmatrix.sync.aligned.m8n8.x4.shared.b16 {%0,%1,%2,%3}, [%4];"
                 : "=r"(a[0]), "=r"(a[1]), "=r"(a[2]), "=r"(a[3]) : "r"(addr));
}
__device__ __forceinline__ void mma16816(float c[4], const u32 a[4], u32 b0, u32 b1) {
    asm volatile(
        "mma.sync.aligned.m16n8k16.row.col.f32.f16.f16.f32 "
        "{%0,%1,%2,%3},{%4,%5,%6,%7},{%8,%9},{%0,%1,%2,%3};"
        : "+f"(c[0]), "+f"(c[1]), "+f"(c[2]), "+f"(c[3])
        : "r"(a[0]), "r"(a[1]), "r"(a[2]), "r"(a[3]), "r"(b0), "r"(b1));
}
__device__ __forceinline__ u16 f2h(float v) { return __half_as_ushort(__float2half_rn(v)); }
__device__ __forceinline__ u32 pack2(float a, float b) {
    return (u32)f2h(a) | ((u32)f2h(b) << 16);
}

// cp.async one 128x32fp16 tile (64B/row) into padded smem
__device__ __forceinline__ void cp_tile(u32 smDst, const char* gSrc, int rowStrideBytes,
                                        int kByteOff, int tid) {
    int row = tid >> 1, seg = (tid & 1) * 32;
    const char* s = gSrc + (size_t)row * rowStrideBytes + kByteOff + seg;
    u32 d = smDst + row * RSB + seg;
    cpa16(d, s);
    cpa16(d + 16, s + 16);
}

// one 32-K chunk, 2-product fp16: A single, B hi+lo; nv = valid cols in tile
__device__ __forceinline__ void compute_chunk(float acc[4][4][4], u32 a_b,
                                              u32 bh_b, u32 bl_b,
                                              int wm, int wn, int lane, int nv) {
    if (wn * 32 >= nv) return;           // whole warp dead (warp-uniform)
    const int rsel = lane & 15;
    const int kbh = (lane >> 4) * 16;
#pragma unroll
    for (int k16 = 0; k16 < 2; k16++) {
        const int kb = k16 * 32 + kbh;
        u32 bh[2][4], bl[2][4];
#pragma unroll
        for (int np = 0; np < 2; np++) {
            if (wn * 32 + np * 16 < nv) {
                u32 off = (u32)(wn * 32 + np * 16 + rsel) * RSB + kb;
                ldsm4(bh[np], bh_b + off);
                ldsm4(bl[np], bl_b + off);
            }
        }
        u32 a[2][4];
        ldsm4(a[0], a_b + (u32)(wm * 64 + rsel) * RSB + kb);
#pragma unroll
        for (int mt = 0; mt < 4; mt++) {
            if (mt < 3)
                ldsm4(a[(mt + 1) & 1], a_b + (u32)(wm * 64 + (mt + 1) * 16 + rsel) * RSB + kb);
            const u32* av = a[mt & 1];
#pragma unroll
            for (int nt = 0; nt < 4; nt++) {
                if (wn * 32 + nt * 8 < nv) {
                    u32 b0h = bh[nt >> 1][nt & 1], b1h = bh[nt >> 1][(nt & 1) + 2];
                    u32 b0l = bl[nt >> 1][nt & 1], b1l = bl[nt >> 1][(nt & 1) + 2];
                    mma16816(acc[mt][nt], av, b0h, b1h);
                    mma16816(acc[mt][nt], av, b0l, b1l);
                }
            }
        }
    }
}

// ---------------- table init (fp16 hi/lo, exact integer phase) ---------------
__global__ void k_init() {
    int idx = blockIdx.x * 256 + threadIdx.x;
    if (idx < CUTF * SEQ) {
        int f = idx / SEQ, t = idx - f * SEQ;
        int r = (f * t) % SEQ;
        float s, cc;
        sincospif((float)r * (1.0f / 360.0f), &s, &cc);
        size_t i0 = (size_t)(2 * f) * KD + t;
        size_t i1 = (size_t)(2 * f + 1) * KD + t;
        __half h0 = __float2half_rn(cc);
        d_Eh[i0] = h0; d_El[i0] = __float2half_rn(cc - __half2float(h0));
        __half h1 = __float2half_rn(-s);
        d_Eh[i1] = h1; d_El[i1] = __float2half_rn(-s - __half2float(h1));
    }
    if (idx < SEQ * FOUT) {
        int tp = idx / FOUT, k = idx - tp * FOUT;
        int t = SEQ + tp;
        int m = (k * t) % 1440;
        float s, cc;
        sincospif((float)m * (1.0f / 720.0f), &s, &cc);
        float fc = (k == 0) ? (1.0f / 720.0f) : (cc * (1.0f / 360.0f));
        float fs = (k == 0) ? 0.0f : (-s * (1.0f / 360.0f));
        size_t i0 = (size_t)tp * KO + 2 * k;
        __half h0 = __float2half_rn(fc);
        d_Fh[i0] = h0; d_Fl[i0] = __float2half_rn(fc - __half2float(h0));
        __half h1 = __float2half_rn(fs);
        d_Fh[i0 + 1] = h1; d_Fl[i0 + 1] = __float2half_rn(fs - __half2float(h1));
    }
}

// ---------------- stats ------------------------------------------------------
__global__ void k_stats(const float* __restrict__ x) {
    int c = blockIdx.x * 256 + threadIdx.x;
    int b = blockIdx.y;
    if (c >= CH) return;
    const float* p = x + (size_t)b * SEQ * CH + c;
    float s = 0.f, ss = 0.f;
    for (int t = 0; t < SEQ; t++) {
        float v = p[(size_t)t * CH];
        s += v;
        ss += v * v;
    }
    float mean = s * (1.0f / SEQ);
    float var = (ss - s * mean) * (1.0f / (SEQ - 1));
    float sd = sqrtf(var + 1e-5f);
    d_mean[b * CH + c] = mean;
    d_stdev[b * CH + c] = sd;
    d_invstd[b * CH + c] = 1.0f / sd;
}

// ---------------- transpose in: x[b][t][c] -> xn[c][b][t] fp16 ---------------
__global__ void k_transpose_in(const float* __restrict__ x) {
    __shared__ float sm[32][33];
    int b = blockIdx.z;
    int c0 = blockIdx.x * 32, t0 = blockIdx.y * 32;
    int tx = threadIdx.x, ty = threadIdx.y;
#pragma unroll
    for (int i = 0; i < 4; i++) {
        int t = t0 + ty + i * 8, c = c0 + tx;
        float v = 0.f;
        if (c < CH && t < SEQ)
            v = (x[(size_t)b * SEQ * CH + (size_t)t * CH + c] - d_mean[b * CH + c]) * d_invstd[b * CH + c];
        sm[ty + i * 8][tx] = v;
    }
    __syncthreads();
#pragma unroll
    for (int i = 0; i < 4; i++) {
        int c = c0 + ty + i * 8;
        int t = t0 + tx;
        if (c < CH && t < SEQ)
            d_xn[((size_t)c * BATCH + b) * KD + t] = __float2half_rn(sm[tx][ty + i * 8]);
    }
}

// ---------------- stage 1: DFT GEMM ------------------------------------------
#define NCH1 23
__global__ __launch_bounds__(256, 2) void k_g1() {
    extern __shared__ char smraw[];
    u32 smb = s2u(smraw);
    const int tid = threadIdx.x, lane = tid & 31, warp = tid >> 5;
    const int wm = warp >> 2, wn = warp & 3;
    const int cidx = blockIdx.z, mBase = blockIdx.y * 128, nBase = blockIdx.x * 128;
    const int nv = 400 - nBase > 128 ? 128 : 400 - nBase;
    const char* gA = (const char*)(d_xn + ((size_t)cidx * BATCH + mBase) * KD);
    const char* gBh = (const char*)(d_Eh + (size_t)nBase * KD);
    const char* gBl = (const char*)(d_El + (size_t)nBase * KD);
    float acc[4][4][4] = {};

#pragma unroll
    for (int p = 0; p < 2; p++) {
        u32 st = smb + p * 3 * TB;
        cp_tile(st + 0 * TB, gA, KD * 2, p * 64, tid);
        cp_tile(st + 1 * TB, gBh, KD * 2, p * 64, tid);
        cp_tile(st + 2 * TB, gBl, KD * 2, p * 64, tid);
        cp_commit();
    }
    int stage = 0;
    for (int ch = 0; ch < NCH1; ch++) {
        if (ch == NCH1 - 1) cp_wait0(); else cp_wait1();
        __syncthreads();
        u32 buf = smb + stage * 3 * TB;
        compute_chunk(acc, buf, buf + TB, buf + 2 * TB, wm, wn, lane, nv);
        if (ch + 2 < NCH1) {
            int ns = stage + 2; if (ns >= 3) ns -= 3;
            u32 nb = smb + ns * 3 * TB;
            int kb = (ch + 2) * 64;
            cp_tile(nb + 0 * TB, gA, KD * 2, kb, tid);
            cp_tile(nb + 1 * TB, gBh, KD * 2, kb, tid);
            cp_tile(nb + 2 * TB, gBl, KD * 2, kb, tid);
            cp_commit();
        }
        if (++stage == 3) stage = 0;
    }
    const int g = lane >> 2, iq = lane & 3;
#pragma unroll
    for (int mt = 0; mt < 4; mt++) {
        int row = mBase + wm * 64 + mt * 16 + g;
        size_t b0 = ((size_t)cidx * BATCH + row) * KX;
        size_t b1 = b0 + 8 * (size_t)KX;
#pragma unroll
        for (int nt = 0; nt < 4; nt++) {
            int col = nBase + wn * 32 + nt * 8 + 2 * iq;
            if (col < 400) {
                float* cc = acc[mt][nt];
                *(u32*)(d_X + b0 + col) = pack2(cc[0], cc[1]);
                *(u32*)(d_X + b1 + col) = pack2(cc[2], cc[3]);
            }
        }
    }
}

// ---------------- stage 2: complex mixer GEMM --------------------------------
// build W2 chunk (128 o2-rows x 32 k2-cols) hi/lo fp16 into smem
__device__ __forceinline__ void build_w2(const float* __restrict__ Wr,
                                         const float* __restrict__ Wi,
                                         int cidx, int nBase, int chunk,
                                         u32 Bh, u32 Bl, int tid) {
    int oloc = tid >> 2;            // 0..63
    int part = tid & 3;             // 4 f values each
    int o = (nBase >> 1) + oloc;
    int f0 = chunk * 16 + part * 4;
    float av[4] = {0.f, 0.f, 0.f, 0.f}, qv[4] = {0.f, 0.f, 0.f, 0.f};
    if (o < FOUT) {
        const float* wr = Wr + ((size_t)cidx * FOUT + o) * CUTF;
        const float* wi = Wi + ((size_t)cidx * FOUT + o) * CUTF;
        if (f0 + 3 < CUTF) {
            float4 wr4 = *(const float4*)(wr + f0);
            float4 wi4 = *(const float4*)(wi + f0);
            av[0] = wr4.x; av[1] = wr4.y; av[2] = wr4.z; av[3] = wr4.w;
            qv[0] = wi4.x; qv[1] = wi4.y; qv[2] = wi4.z; qv[3] = wi4.w;
        } else {
#pragma unroll
            for (int j = 0; j < 4; j++)
                if (f0 + j < CUTF) { av[j] = wr[f0 + j]; qv[j] = wi[f0 + j]; }
        }
    }
    u32 he[4], le[4], ho[4], lo[4];
#pragma unroll
    for (int j = 0; j < 4; j++) {
        float e0 = av[j], e1 = -qv[j];
        float o0 = qv[j], o1 = av[j];
        __half e0h = __float2half_rn(e0), e1h = __float2half_rn(e1);
        __half o0h = __float2half_rn(o0), o1h = __float2half_rn(o1);
        he[j] = (u32)__half_as_ushort(e0h) | ((u32)__half_as_ushort(e1h) << 16);
        ho[j] = (u32)__half_as_ushort(o0h) | ((u32)__half_as_ushort(o1h) << 16);
        le[j] = pack2(e0 - __half2float(e0h), e1 - __half2float(e1h));
        lo[j] = pack2(o0 - __half2float(o0h), o1 - __half2float(o1h));
    }
    u32 offE = (u32)(2 * oloc) * RSB + part * 16;
    u32 offO = offE + RSB;
    asm volatile("st.shared.v4.b32 [%0], {%1,%2,%3,%4};" :: "r"(Bh + offE), "r"(he[0]), "r"(he[1]), "r"(he[2]), "r"(he[3]));
    asm volatile("st.shared.v4.b32 [%0], {%1,%2,%3,%4};" :: "r"(Bl + offE), "r"(le[0]), "r"(le[1]), "r"(le[2]), "r"(le[3]));
    asm volatile("st.shared.v4.b32 [%0], {%1,%2,%3,%4};" :: "r"(Bh + offO), "r"(ho[0]), "r"(ho[1]), "r"(ho[2]), "r"(ho[3]));
    asm volatile("st.shared.v4.b32 [%0], {%1,%2,%3,%4};" :: "r"(Bl + offO), "r"(lo[0]), "r"(lo[1]), "r"(lo[2]), "r"(lo[3]));
}

#define NCH2 13
__global__ __launch_bounds__(256, 2) void k_g2(const float* __restrict__ Wr,
                                               const float* __restrict__ Wi,
                                               const float* __restrict__ br,
                                               const float* __restrict__ bi) {
    extern __shared__ char smraw[];
    u32 smb = s2u(smraw);
    const int tid = threadIdx.x, lane = tid & 31, warp = tid >> 5;
    const int wm = warp >> 2, wn = warp & 3;
    const int cidx = blockIdx.z, mBase = blockIdx.y * 128, nBase = blockIdx.x * 128;
    const int nv = 800 - nBase > 128 ? 128 : 800 - nBase;
    const char* gA = (const char*)(d_X + ((size_t)cidx * BATCH + mBase) * KX);
    float acc[4][4][4] = {};

#pragma unroll
    for (int p = 0; p < 2; p++) {
        u32 st = smb + p * 3 * TB;
        cp_tile(st + 0 * TB, gA, KX * 2, p * 64, tid);
        cp_commit();
        build_w2(Wr, Wi, cidx, nBase, p, st + 1 * TB, st + 2 * TB, tid);
    }
    int stage = 0;
    for (int ch = 0; ch < NCH2; ch++) {
        if (ch == NCH2 - 1) cp_wait0(); else cp_wait1();
        __syncthreads();
        u32 buf = smb + stage * 3 * TB;
        compute_chunk(acc, buf, buf + TB, buf + 2 * TB, wm, wn, lane, nv);
        if (ch + 2 < NCH2) {
            int ns = stage + 2; if (ns >= 3) ns -= 3;
            u32 nb = smb + ns * 3 * TB;
            cp_tile(nb + 0 * TB, gA, KX * 2, (ch + 2) * 64, tid);
            cp_commit();
            build_w2(Wr, Wi, cidx, nBase, ch + 2, nb + 1 * TB, nb + 2 * TB, tid);
        }
        if (++stage == 3) stage = 0;
    }
    const int g = lane >> 2, iq = lane & 3;
    const float* brp = br + (size_t)cidx * FOUT;
    const float* bip = bi + (size_t)cidx * FOUT;
#pragma unroll
    for (int mt = 0; mt < 4; mt++) {
        int row = mBase + wm * 64 + mt * 16 + g;
        size_t b0 = ((size_t)cidx * BATCH + row) * KO;
        size_t b1 = b0 + 8 * (size_t)KO;
#pragma unroll
        for (int nt = 0; nt < 4; nt++) {
            int col = nBase + wn * 32 + nt * 8 + 2 * iq;
            if (col < 800) {
                int o = col >> 1;
                float vr = brp[o], vi = bip[o];
                float* cc = acc[mt][nt];
                *(u32*)(d_O + b0 + col) = pack2(cc[0] + vr, cc[1] + vi);
                *(u32*)(d_O + b1 + col) = pack2(cc[2] + vr, cc[3] + vi);
            }
        }
    }
}

// ---------------- stage 3: irfft GEMM ----------------------------------------
#define NCH3 25
__global__ __launch_bounds__(256, 2) void k_g3() {
    extern __shared__ char smraw[];
    u32 smb = s2u(smraw);
    const int tid = threadIdx.x, lane = tid & 31, warp = tid >> 5;
    const int wm = warp >> 2, wn = warp & 3;
    const int cidx = blockIdx.z, mBase = blockIdx.y * 128, nBase = blockIdx.x * 128;
    const int nv = 720 - nBase > 128 ? 128 : 720 - nBase;
    const char* gA = (const char*)(d_O + ((size_t)cidx * BATCH + mBase) * KO);
    const char* gBh = (const char*)(d_Fh + (size_t)nBase * KO);
    const char* gBl = (const char*)(d_Fl + (size_t)nBase * KO);
    float acc[4][4][4] = {};

#pragma unroll
    for (int p = 0; p < 2; p++) {
        u32 st = smb + p * 3 * TB;
        cp_tile(st + 0 * TB, gA, KO * 2, p * 64, tid);
        cp_tile(st + 1 * TB, gBh, KO * 2, p * 64, tid);
        cp_tile(st + 2 * TB, gBl, KO * 2, p * 64, tid);
        cp_commit();
    }
    int stage = 0;
    for (int ch = 0; ch < NCH3; ch++) {
        if (ch == NCH3 - 1) cp_wait0(); else cp_wait1();
        __syncthreads();
        u32 buf = smb + stage * 3 * TB;
        compute_chunk(acc, buf, buf + TB, buf + 2 * TB, wm, wn, lane, nv);
        if (ch + 2 < NCH3) {
            int ns = stage + 2; if (ns >= 3) ns -= 3;
            u32 nb = smb + ns * 3 * TB;
            int kb = (ch + 2) * 64;
            cp_tile(nb + 0 * TB, gA, KO * 2, kb, tid);
            cp_tile(nb + 1 * TB, gBh, KO * 2, kb, tid);
            cp_tile(nb + 2 * TB, gBl, KO * 2, kb, tid);
            cp_commit();
        }
        if (++stage == 3) stage = 0;
    }
    const int g = lane >> 2, iq = lane & 3;
#pragma unroll
    for (int mt = 0; mt < 4; mt++) {
        int row = mBase + wm * 64 + mt * 16 + g;
        float* y0 = d_y + ((size_t)cidx * BATCH + row) * SEQ;
        float* y1 = y0 + 8 * (size_t)SEQ;
#pragma unroll
        for (int nt = 0; nt < 4; nt++) {
            int col = nBase + wn * 32 + nt * 8 + 2 * iq;
            if (col < SEQ) {
                float* cc = acc[mt][nt];
                *(float2*)(y0 + col) = make_float2(cc[0], cc[1]);
                *(float2*)(y1 + col) = make_float2(cc[2], cc[3]);
            }
        }
    }
}

// ---------------- transpose out: y[c][b][t] -> out[b][t][c], de-norm ---------
__global__ void k_transpose_out(float* __restrict__ out) {
    __shared__ float sm[32][33];
    int b = blockIdx.z;
    int c0 = blockIdx.x * 32, t0 = blockIdx.y * 32;
    int tx = threadIdx.x, ty = threadIdx.y;
#pragma unroll
    for (int i = 0; i < 4; i++) {
        int c = c0 + ty + i * 8;
        int t = t0 + tx;
        float v = 0.f;
        if (c < CH && t < SEQ)
            v = d_y[((size_t)c * BATCH + b) * SEQ + t];
        sm[ty + i * 8][tx] = v;
    }
    __syncthreads();
#pragma unroll
    for (int i = 0; i < 4; i++) {
        int t = t0 + ty + i * 8;
        int c = c0 + tx;
        if (t < SEQ && c < CH) {
            float v = sm[tx][ty + i * 8];
            out[(size_t)b * SEQ * CH + (size_t)t * CH + c] =
                v * d_stdev[b * CH + c] + d_mean[b * CH + c];
        }
    }
}

// ---------------- launch -----------------------------------------------------
extern "C" void kernel_launch(void* const* d_in, const int* in_sizes, int n_in,
                              void* d_out, int out_size) {
    const float* x_enc = (const float*)d_in[0];
    const float* Wr = (const float*)d_in[4];
    const float* Wi = (const float*)d_in[5];
    const float* br = (const float*)d_in[6];
    const float* bi = (const float*)d_in[7];
    float* out = (float*)d_out;

    static int attrDone = 0;
    if (!attrDone) {
        cudaFuncSetAttribute(k_g1, cudaFuncAttributeMaxDynamicSharedMemorySize, SMEM_BYTES);
        cudaFuncSetAttribute(k_g2, cudaFuncAttributeMaxDynamicSharedMemorySize, SMEM_BYTES);
        cudaFuncSetAttribute(k_g3, cudaFuncAttributeMaxDynamicSharedMemorySize, SMEM_BYTES);
        attrDone = 1;
    }

    k_init<<<1125, 256>>>();
    k_stats<<<dim3(2, BATCH), 256>>>(x_enc);
    k_transpose_in<<<dim3(11, 23, BATCH), dim3(32, 8)>>>(x_enc);
    k_g1<<<dim3(4, 2, CH), 256, SMEM_BYTES>>>();
    k_g2<<<dim3(7, 2, CH), 256, SMEM_BYTES>>>(Wr, Wi, br, bi);
    k_g3<<<dim3(6, 2, CH), 256, SMEM_BYTES>>>();
    k_transpose_out<<<dim3(11, 23, BATCH), dim3(32, 8)>>>(out);
}